// round 11
// baseline (speedup 1.0000x reference)
#include <cuda_runtime.h>
#include <cuda_fp16.h>
#include <cstdint>

#define BB 4
#define NN 4096
#define CC 1024
#define NH 8
#define HC 128
#define OO 2048
#define NSEG 8

// Scratch (device globals; no allocation allowed)
__device__ __align__(256) __half g_Qh[BB*CC*NN];
__device__ __align__(256) __half g_Kh[BB*CC*NN];
__device__ __align__(256) __half g_x1h[BB*NN*CC];
__device__ __align__(256) __half g_Sh[BB*NH*HC*HC];    // S^T[j][i] fp16
__device__ __align__(256) float  g_Sp[NSEG*BB*NH*HC*HC];
__device__ __align__(256) __half g_Th[BB*OO*CC];       // [b][o][c'] fp16
__device__ __align__(256) __half g_yh[BB*NN*OO];
__device__ __align__(256) __half g_wh[OO*CC];
__device__ float g_cmax[BB*CC];
__device__ float g_cinv[BB*CC];

// ---------------------------------------------------------------- helpers
__device__ __forceinline__ uint32_t s2u(const void* p) {
    uint32_t a;
    asm("{ .reg .u64 t; cvta.to.shared.u64 t, %1; cvt.u32.u64 %0, t; }" : "=r"(a) : "l"(p));
    return a;
}
__device__ __forceinline__ void cp16(uint32_t d, const void* s) {
    asm volatile("cp.async.cg.shared.global [%0], [%1], 16;" :: "r"(d), "l"(s));
}
#define CP_COMMIT() asm volatile("cp.async.commit_group;" ::: "memory")
#define CP_WAIT0()  asm volatile("cp.async.wait_group 0;" ::: "memory")
#define CP_WAIT1()  asm volatile("cp.async.wait_group 1;" ::: "memory")
#define SWZ(o)   ((o) ^ (((o) >> 3) & 0x70))

__device__ __forceinline__ void ldsm4(uint32_t* r, uint32_t addr) {
    asm volatile("ldmatrix.sync.aligned.m8n8.x4.shared.b16 {%0,%1,%2,%3}, [%4];"
        : "=r"(r[0]), "=r"(r[1]), "=r"(r[2]), "=r"(r[3]) : "r"(addr));
}
__device__ __forceinline__ void mma_h(float* c, const uint32_t* a, const uint32_t* b) {
    asm volatile("mma.sync.aligned.m16n8k16.row.col.f32.f16.f16.f32 "
        "{%0,%1,%2,%3}, {%4,%5,%6,%7}, {%8,%9}, {%0,%1,%2,%3};"
        : "+f"(c[0]), "+f"(c[1]), "+f"(c[2]), "+f"(c[3])
        : "r"(a[0]), "r"(a[1]), "r"(a[2]), "r"(a[3]), "r"(b[0]), "r"(b[1]));
}

// fp16 warp tile 64(m) x 64(n) over one k=64 tile (rows = 128B, SW128)
__device__ __forceinline__ void warp_mma_h64(uint32_t sbA, uint32_t sbB, int wm, int wn,
                                             int lane, float (&acc)[4][8][4]) {
    int rA = lane & 15, cA = (lane & 16);
    int rB = (lane & 7) + ((lane & 16) >> 1), cB = (lane & 8) << 1;
    #pragma unroll
    for (int s = 0; s < 4; s++) {
        uint32_t a[4][4], b[4][4];
        #pragma unroll
        for (int mi = 0; mi < 4; mi++)
            ldsm4(a[mi], sbA + SWZ((wm * 64 + mi * 16 + rA) * 128 + s * 32 + cA));
        #pragma unroll
        for (int nj = 0; nj < 4; nj++)
            ldsm4(b[nj], sbB + SWZ((wn * 64 + nj * 16 + rB) * 128 + s * 32 + cB));
        #pragma unroll
        for (int mi = 0; mi < 4; mi++)
            #pragma unroll
            for (int ni = 0; ni < 8; ni++)
                mma_h(acc[mi][ni], a[mi], &b[ni >> 1][(ni & 1) * 2]);
    }
}

// fp16 warp tile 64(m) x 32(n) over one k=64 tile (rows = 128B, SW128)
__device__ __forceinline__ void warp_mma_h32(uint32_t sbA, uint32_t sbB, int wm, int wn,
                                             int lane, float (&acc)[4][4][4]) {
    int rA = lane & 15, cA = (lane & 16);
    int rB = (lane & 7) + ((lane & 16) >> 1), cB = (lane & 8) << 1;
    #pragma unroll
    for (int s = 0; s < 4; s++) {
        uint32_t a[4][4], b[2][4];
        #pragma unroll
        for (int mi = 0; mi < 4; mi++)
            ldsm4(a[mi], sbA + SWZ((wm * 64 + mi * 16 + rA) * 128 + s * 32 + cA));
        #pragma unroll
        for (int nj = 0; nj < 2; nj++)
            ldsm4(b[nj], sbB + SWZ((wn * 32 + nj * 16 + rB) * 128 + s * 32 + cB));
        #pragma unroll
        for (int mi = 0; mi < 4; mi++)
            #pragma unroll
            for (int ni = 0; ni < 4; ni++)
                mma_h(acc[mi][ni], a[mi], &b[ni >> 1][(ni & 1) * 2]);
    }
}

__device__ __forceinline__ void store_acc64f(float* out, int ld, float (&acc)[4][8][4],
                                             int wm, int wn, int lane) {
    int r0 = wm * 64 + (lane >> 2), col0 = wn * 64 + 2 * (lane & 3);
    #pragma unroll
    for (int mi = 0; mi < 4; mi++)
        #pragma unroll
        for (int ni = 0; ni < 8; ni++) {
            float* c = acc[mi][ni];
            *(float2*)&out[(size_t)(r0 + mi * 16) * ld + col0 + ni * 8] = make_float2(c[0], c[1]);
            *(float2*)&out[(size_t)(r0 + mi * 16 + 8) * ld + col0 + ni * 8] = make_float2(c[2], c[3]);
        }
}
__device__ __forceinline__ void store_acc64h(__half* out, int ld, float (&acc)[4][8][4],
                                             int wm, int wn, int lane) {
    int r0 = wm * 64 + (lane >> 2), col0 = wn * 64 + 2 * (lane & 3);
    #pragma unroll
    for (int mi = 0; mi < 4; mi++)
        #pragma unroll
        for (int ni = 0; ni < 8; ni++) {
            float* c = acc[mi][ni];
            *(__half2*)&out[(size_t)(r0 + mi * 16) * ld + col0 + ni * 8] = __floats2half2_rn(c[0], c[1]);
            *(__half2*)&out[(size_t)(r0 + mi * 16 + 8) * ld + col0 + ni * 8] = __floats2half2_rn(c[2], c[3]);
        }
}
__device__ __forceinline__ void store_acc32h(__half* out, int ld, float (&acc)[4][4][4],
                                             int wm, int wn, int lane) {
    int r0 = wm * 64 + (lane >> 2), col0 = wn * 32 + 2 * (lane & 3);
    #pragma unroll
    for (int mi = 0; mi < 4; mi++)
        #pragma unroll
        for (int ni = 0; ni < 4; ni++) {
            float* c = acc[mi][ni];
            *(__half2*)&out[(size_t)(r0 + mi * 16) * ld + col0 + ni * 8] = __floats2half2_rn(c[0], c[1]);
            *(__half2*)&out[(size_t)(r0 + mi * 16 + 8) * ld + col0 + ni * 8] = __floats2half2_rn(c[2], c[3]);
        }
}

// ---------------------------------------------------------------------------
// 1) FUSED: fp16 conversion of w & x1 (blocks [0, NB_CVT)) +
//           column softmax stats for "key" (blocks [NB_CVT, NB_CVT+128))
// ---------------------------------------------------------------------------
#define WF4  (OO * CC / 4)
#define X1F4 (BB * NN * CC / 4)
#define NB_CVT ((WF4 + X1F4) / 256)
__global__ void pre_k(const float* __restrict__ w, const float* __restrict__ x1,
                      const float* __restrict__ x2) {
    int bid = blockIdx.x;
    if (bid < NB_CVT) {
        int i = bid * 256 + threadIdx.x;
        if (i < WF4) {
            float4 v = ((const float4*)w)[i];
            ((__half2*)g_wh)[2 * i] = __floats2half2_rn(v.x, v.y);
            ((__half2*)g_wh)[2 * i + 1] = __floats2half2_rn(v.z, v.w);
        } else {
            int j = i - WF4;
            float4 v = ((const float4*)x1)[j];
            ((__half2*)g_x1h)[2 * j] = __floats2half2_rn(v.x, v.y);
            ((__half2*)g_x1h)[2 * j + 1] = __floats2half2_rn(v.z, v.w);
        }
        return;
    }
    int cb = bid - NB_CVT;             // 0..127
    int b = cb >> 5;                   // 4 batches
    int chb = cb & 31;                 // 32 channel-blocks of 32
    int tx = threadIdx.x & 31, ty = threadIdx.x >> 5;   // (32, 8)
    int ch = chb * 32 + tx;
    const float* p = x2 + (size_t)b * NN * CC + ch;
    float m = -1e30f, s = 0.f;
    for (int n = ty; n < NN; n += 8) {
        float v = p[(size_t)n * CC];
        float mn = fmaxf(m, v);
        s = s * __expf(m - mn) + __expf(v - mn);
        m = mn;
    }
    __shared__ float sm_[8][32], ss_[8][32];
    sm_[ty][tx] = m;
    ss_[ty][tx] = s;
    __syncthreads();
    if (ty == 0) {
        for (int r = 1; r < 8; r++) {
            float m2 = sm_[r][tx], s2 = ss_[r][tx];
            float mn = fmaxf(m, m2);
            s = s * __expf(m - mn) + s2 * __expf(m2 - mn);
            m = mn;
        }
        g_cmax[b * CC + ch] = m;
        g_cinv[b * CC + ch] = 1.f / s;
    }
}

// ---------------------------------------------------------------------------
// 2) Prep: transpose + both softmaxes, write Q, K as [b,h,c,N] fp16
// ---------------------------------------------------------------------------
__global__ void prep_k(const float* __restrict__ x2) {
    __shared__ float t[HC][33];
    __shared__ float tmx[32], tsi[32];
    int b = blockIdx.y, n0 = blockIdx.x * 32;
    int tid = threadIdx.x;
    int w = tid >> 5, l = tid & 31;
    for (int hd = 0; hd < NH; hd++) {
        const float* src = x2 + ((size_t)(b * NN + n0)) * CC + hd * HC;
        #pragma unroll
        for (int k = 0; k < 16; k++) {
            int e = tid + 256 * k; int i = e & 127, tt = e >> 7;
            t[i][tt] = src[(size_t)tt * CC + i];
        }
        __syncthreads();
        #pragma unroll
        for (int q = 0; q < 4; q++) {
            int tok = w * 4 + q;
            float v0 = t[l][tok], v1 = t[l + 32][tok], v2 = t[l + 64][tok], v3 = t[l + 96][tok];
            float m = fmaxf(fmaxf(v0, v1), fmaxf(v2, v3));
            #pragma unroll
            for (int o = 16; o; o >>= 1) m = fmaxf(m, __shfl_xor_sync(0xffffffffu, m, o));
            float s = __expf(v0 - m) + __expf(v1 - m) + __expf(v2 - m) + __expf(v3 - m);
            #pragma unroll
            for (int o = 16; o; o >>= 1) s += __shfl_xor_sync(0xffffffffu, s, o);
            if (l == 0) { tmx[tok] = m; tsi[tok] = 1.f / s; }
        }
        __syncthreads();
        __half* Qd = g_Qh + ((size_t)(b * NH + hd)) * HC * NN + n0;
        __half* Kd = g_Kh + ((size_t)(b * NH + hd)) * HC * NN + n0;
        const float* cm = g_cmax + b * CC + hd * HC;
        const float* ci = g_cinv + b * CC + hd * HC;
        #pragma unroll
        for (int k = 0; k < 8; k++) {
            int e = tid + 256 * k;
            int tp = (e & 15) * 2, i = e >> 4;
            float va = t[i][tp], vb = t[i][tp + 1];
            float qa = __expf(va - tmx[tp]) * tsi[tp];
            float qb = __expf(vb - tmx[tp + 1]) * tsi[tp + 1];
            float ka = __expf(va - cm[i]) * ci[i];
            float kb = __expf(vb - cm[i]) * ci[i];
            *(__half2*)(Qd + (size_t)i * NN + tp) = __floats2half2_rn(qa, qb);
            *(__half2*)(Kd + (size_t)i * NN + tp) = __floats2half2_rn(ka, kb);
        }
        __syncthreads();
    }
}

// ---------------------------------------------------------------------------
// 3) GEMM1 (split-K): Sp^T[seg][j][i] = K_j . Q_i   M=128(j) N=128(i) K=512
// ---------------------------------------------------------------------------
__global__ void __launch_bounds__(128) gemm1_k() {
    extern __shared__ char smbuf[];
    uint32_t sb = s2u(smbuf);
    int tid = threadIdx.x, lane = tid & 31, wid = tid >> 5;
    int wm = wid >> 1, wn = wid & 1;
    int seg = blockIdx.x, bh = blockIdx.y;
    const __half* Ag = g_Kh + (size_t)bh * HC * NN;
    const __half* Bg = g_Qh + (size_t)bh * HC * NN;
    int kbase = seg * (NN / NSEG);
    float acc[4][8][4] = {};
    for (int q = tid; q < 1024; q += 128) {
        int r = q >> 3, c = q & 7;
        cp16(sb + SWZ(r * 128 + c * 16), Ag + (size_t)r * NN + kbase + c * 8);
        cp16(sb + 16384 + SWZ(r * 128 + c * 16), Bg + (size_t)r * NN + kbase + c * 8);
    }
    CP_COMMIT();
    for (int t = 0; t < 8; t++) {
        if (t + 1 < 8) {
            uint32_t nb = sb + ((t + 1) & 1) * 32768;
            int k0 = kbase + (t + 1) * 64;
            for (int q = tid; q < 1024; q += 128) {
                int r = q >> 3, c = q & 7;
                cp16(nb + SWZ(r * 128 + c * 16), Ag + (size_t)r * NN + k0 + c * 8);
                cp16(nb + 16384 + SWZ(r * 128 + c * 16), Bg + (size_t)r * NN + k0 + c * 8);
            }
            CP_COMMIT();
            CP_WAIT1();
        } else CP_WAIT0();
        __syncthreads();
        uint32_t cb = sb + (t & 1) * 32768;
        warp_mma_h64(cb, cb + 16384, wm, wn, lane, acc);
        __syncthreads();
    }
    float* out = g_Sp + ((size_t)(seg * BB * NH + bh)) * HC * HC;
    store_acc64f(out, HC, acc, wm, wn, lane);
}

__global__ void reduceS_k() {
    int i = blockIdx.x * 256 + threadIdx.x;
    float s = 0.f;
    #pragma unroll
    for (int r = 0; r < NSEG; r++) s += g_Sp[(size_t)r * (BB * NH * HC * HC) + i];
    g_Sh[i] = __float2half_rn(s);
}

// ---------------------------------------------------------------------------
// 4) GEMMT: T[b][o][h*128+j] = sum_c w[o, h*128+c] * S[c,j]
// ---------------------------------------------------------------------------
__global__ void __launch_bounds__(128) gemmT_k() {
    extern __shared__ char smbuf[];
    uint32_t sb = s2u(smbuf);
    int tid = threadIdx.x, lane = tid & 31, wid = tid >> 5;
    int wm = wid >> 1, wn = wid & 1;
    int o0 = blockIdx.x * 128, bh = blockIdx.y;
    int b = bh >> 3, hd = bh & 7;
    const __half* Ag = g_wh + (size_t)o0 * CC + hd * HC;
    const __half* Bg = g_Sh + (size_t)bh * HC * HC;
    float acc[4][8][4] = {};
    for (int q = tid; q < 1024; q += 128) {
        int r = q >> 3, c = q & 7;
        cp16(sb + SWZ(r * 128 + c * 16), Ag + (size_t)r * CC + c * 8);
        cp16(sb + 16384 + SWZ(r * 128 + c * 16), Bg + (size_t)r * HC + c * 8);
    }
    CP_COMMIT();
    for (int t = 0; t < 2; t++) {
        if (t + 1 < 2) {
            int k0 = (t + 1) * 64;
            uint32_t nb = sb + 32768;
            for (int q = tid; q < 1024; q += 128) {
                int r = q >> 3, c = q & 7;
                cp16(nb + SWZ(r * 128 + c * 16), Ag + (size_t)r * CC + k0 + c * 8);
                cp16(nb + 16384 + SWZ(r * 128 + c * 16), Bg + (size_t)r * HC + k0 + c * 8);
            }
            CP_COMMIT();
            CP_WAIT1();
        } else CP_WAIT0();
        __syncthreads();
        uint32_t cb = sb + (t & 1) * 32768;
        warp_mma_h64(cb, cb + 16384, wm, wn, lane, acc);
        __syncthreads();
    }
    __half* out = g_Th + ((size_t)b * OO + o0) * CC + hd * HC;
    store_acc64h(out, CC, acc, wm, wn, lane);
}

// ---------------------------------------------------------------------------
// 5) GEMMF (dominant, at HMMA issue floor): y[n][o] = sum_c' x1h[n][c'] * T[b][o][c']
//    M=128(tok) N=256(o) K=1024; 512 threads (16 warps, warp tile 64x32),
//    2-stage k=64 double buffering, SW128.  (R8-proven configuration)
// ---------------------------------------------------------------------------
__global__ void __launch_bounds__(512) gemmF_k() {
    extern __shared__ char smbuf[];
    uint32_t sb = s2u(smbuf);
    int tid = threadIdx.x, lane = tid & 31, wid = tid >> 5;
    int wm = wid & 1, wn = wid >> 1;     // wm 0..1 (64 rows each), wn 0..7 (32 cols each)
    int m0 = blockIdx.x * 128, o0 = blockIdx.y * 256;
    int b = m0 >> 12;
    const __half* Ag = g_x1h + (size_t)m0 * CC;
    const __half* Bg = g_Th + ((size_t)b * OO + o0) * CC;
    float acc[4][4][4] = {};
    // buffers: stride 49152; A @ +0 (16KB), B @ +16384 (32KB)
    for (int q = tid; q < 1024; q += 512) {
        int r = q >> 3, c = q & 7;
        cp16(sb + SWZ(r * 128 + c * 16), Ag + (size_t)r * CC + c * 8);
    }
    for (int q = tid; q < 2048; q += 512) {
        int r = q >> 3, c = q & 7;
        cp16(sb + 16384 + SWZ(r * 128 + c * 16), Bg + (size_t)r * CC + c * 8);
    }
    CP_COMMIT();
    for (int t = 0; t < 16; t++) {
        if (t + 1 < 16) {
            int k0 = (t + 1) * 64;
            uint32_t nb = sb + ((t + 1) & 1) * 49152;
            for (int q = tid; q < 1024; q += 512) {
                int r = q >> 3, c = q & 7;
                cp16(nb + SWZ(r * 128 + c * 16), Ag + (size_t)r * CC + k0 + c * 8);
            }
            for (int q = tid; q < 2048; q += 512) {
                int r = q >> 3, c = q & 7;
                cp16(nb + 16384 + SWZ(r * 128 + c * 16), Bg + (size_t)r * CC + k0 + c * 8);
            }
            CP_COMMIT();
            CP_WAIT1();
        } else CP_WAIT0();
        __syncthreads();
        uint32_t cb = sb + (t & 1) * 49152;
        warp_mma_h32(cb, cb + 16384, wm, wn, lane, acc);
        __syncthreads();
    }
    __half* out = g_yh + (size_t)m0 * OO + o0;
    store_acc32h(out, OO, acc, wm, wn, lane);
}

// ---------------------------------------------------------------------------
// 6) Fused bias + LayerNorm over O=2048 (reads fp16 y)
// ---------------------------------------------------------------------------
__global__ void ln_k(float* __restrict__ out, const float* __restrict__ bp,
                     const float* __restrict__ gm, const float* __restrict__ bt) {
    int t = blockIdx.x;
    const __half2* y2 = (const __half2*)(g_yh + (size_t)t * OO);
    int tid = threadIdx.x;
    float v[8];
    float s = 0.f, sq = 0.f;
    #pragma unroll
    for (int k = 0; k < 4; k++) {
        int idx = tid + 256 * k;
        float2 xv = __half22float2(y2[idx]);
        float xa = xv.x + bp[2 * idx], xb = xv.y + bp[2 * idx + 1];
        v[2 * k] = xa; v[2 * k + 1] = xb;
        s += xa + xb; sq += xa * xa + xb * xb;
    }
    #pragma unroll
    for (int o = 16; o; o >>= 1) {
        s += __shfl_xor_sync(0xffffffffu, s, o);
        sq += __shfl_xor_sync(0xffffffffu, sq, o);
    }
    __shared__ float rs[8], rq[8];
    if ((tid & 31) == 0) { rs[tid >> 5] = s; rq[tid >> 5] = sq; }
    __syncthreads();
    if (tid < 8) {
        float a = rs[tid], b2 = rq[tid];
        #pragma unroll
        for (int o = 4; o; o >>= 1) {
            a += __shfl_xor_sync(0x000000ffu, a, o);
            b2 += __shfl_xor_sync(0x000000ffu, b2, o);
        }
        if (tid == 0) { rs[0] = a; rq[0] = b2; }
    }
    __syncthreads();
    float mean = rs[0] * (1.f / OO);
    float var = rq[0] * (1.f / OO) - mean * mean;
    float rstd = rsqrtf(var + 1e-5f);
    float* op = out + (size_t)t * OO;
    #pragma unroll
    for (int k = 0; k < 4; k++) {
        int idx = tid + 256 * k;
        int o = 2 * idx;
        float2 r = make_float2((v[2 * k] - mean) * rstd * gm[o] + bt[o],
                               (v[2 * k + 1] - mean) * rstd * gm[o + 1] + bt[o + 1]);
        *(float2*)&op[o] = r;
    }
}

extern "C" void kernel_launch(void* const* d_in, const int* in_sizes, int n_in,
                              void* d_out, int out_size) {
    const float* x1 = (const float*)d_in[0];
    const float* x2 = (const float*)d_in[1];
    const float* w  = (const float*)d_in[2];
    const float* bp = (const float*)d_in[3];
    const float* gm = (const float*)d_in[4];
    const float* bt = (const float*)d_in[5];
    float* out = (float*)d_out;

    const int SMG = 65536;   // gemm1/gemmT: 2 x (16KB + 16KB)
    const int SMF = 98304;   // gemmF: 2 x (16KB + 32KB)
    cudaFuncSetAttribute(gemm1_k, cudaFuncAttributeMaxDynamicSharedMemorySize, SMG);
    cudaFuncSetAttribute(gemmT_k, cudaFuncAttributeMaxDynamicSharedMemorySize, SMG);
    cudaFuncSetAttribute(gemmF_k, cudaFuncAttributeMaxDynamicSharedMemorySize, SMF);

    pre_k<<<NB_CVT + 128, 256>>>(w, x1, x2);
    prep_k<<<dim3(NN / 32, BB), 256>>>(x2);
    gemm1_k<<<dim3(NSEG, BB * NH), 128, SMG>>>();
    reduceS_k<<<(BB * NH * HC * HC) / 256, 256>>>();
    gemmT_k<<<dim3(OO / 128, BB * NH), 128, SMG>>>();
    gemmF_k<<<dim3(BB * NN / 128, OO / 256), 512, SMF>>>();
    ln_k<<<BB * NN, 256>>>(out, bp, gm, bt);
}

// round 14
// speedup vs baseline: 1.0657x; 1.0657x over previous
#include <cuda_runtime.h>
#include <cuda_fp16.h>
#include <cstdint>

#define BB 4
#define NN 4096
#define CC 1024
#define NH 8
#define HC 128
#define OO 2048
#define NSEG 8

// Scratch (device globals; no allocation allowed)
__device__ __align__(256) __half g_Qh[BB*CC*NN];
__device__ __align__(256) __half g_Kh[BB*CC*NN];
__device__ __align__(256) __half g_x1h[BB*NN*CC];
__device__ __align__(256) __half g_Sh[BB*NH*HC*HC];    // S^T[j][i] fp16
__device__ __align__(256) float  g_Sp[NSEG*BB*NH*HC*HC];
__device__ __align__(256) __half g_Th[BB*OO*CC];       // [b][o][c'] fp16
__device__ __align__(256) __half g_yh[BB*NN*OO];
__device__ __align__(256) __half g_wh[OO*CC];
__device__ float g_cmax[BB*CC];
__device__ float g_cinv[BB*CC];

// ---------------------------------------------------------------- helpers
__device__ __forceinline__ uint32_t s2u(const void* p) {
    uint32_t a;
    asm("{ .reg .u64 t; cvta.to.shared.u64 t, %1; cvt.u32.u64 %0, t; }" : "=r"(a) : "l"(p));
    return a;
}
__device__ __forceinline__ void cp16(uint32_t d, const void* s) {
    asm volatile("cp.async.cg.shared.global [%0], [%1], 16;" :: "r"(d), "l"(s));
}
#define CP_COMMIT() asm volatile("cp.async.commit_group;" ::: "memory")
#define CP_WAIT0()  asm volatile("cp.async.wait_group 0;" ::: "memory")
#define CP_WAIT1()  asm volatile("cp.async.wait_group 1;" ::: "memory")
#define SWZ(o)   ((o) ^ (((o) >> 3) & 0x70))

__device__ __forceinline__ void ldsm4(uint32_t* r, uint32_t addr) {
    asm volatile("ldmatrix.sync.aligned.m8n8.x4.shared.b16 {%0,%1,%2,%3}, [%4];"
        : "=r"(r[0]), "=r"(r[1]), "=r"(r[2]), "=r"(r[3]) : "r"(addr));
}
__device__ __forceinline__ void mma_h(float* c, const uint32_t* a, const uint32_t* b) {
    asm volatile("mma.sync.aligned.m16n8k16.row.col.f32.f16.f16.f32 "
        "{%0,%1,%2,%3}, {%4,%5,%6,%7}, {%8,%9}, {%0,%1,%2,%3};"
        : "+f"(c[0]), "+f"(c[1]), "+f"(c[2]), "+f"(c[3])
        : "r"(a[0]), "r"(a[1]), "r"(a[2]), "r"(a[3]), "r"(b[0]), "r"(b[1]));
}

// fp16 warp tile 64(m) x 64(n) over one k=64 tile (rows = 128B, SW128)
__device__ __forceinline__ void warp_mma_h64(uint32_t sbA, uint32_t sbB, int wm, int wn,
                                             int lane, float (&acc)[4][8][4]) {
    int rA = lane & 15, cA = (lane & 16);
    int rB = (lane & 7) + ((lane & 16) >> 1), cB = (lane & 8) << 1;
    #pragma unroll
    for (int s = 0; s < 4; s++) {
        uint32_t a[4][4], b[4][4];
        #pragma unroll
        for (int mi = 0; mi < 4; mi++)
            ldsm4(a[mi], sbA + SWZ((wm * 64 + mi * 16 + rA) * 128 + s * 32 + cA));
        #pragma unroll
        for (int nj = 0; nj < 4; nj++)
            ldsm4(b[nj], sbB + SWZ((wn * 64 + nj * 16 + rB) * 128 + s * 32 + cB));
        #pragma unroll
        for (int mi = 0; mi < 4; mi++)
            #pragma unroll
            for (int ni = 0; ni < 8; ni++)
                mma_h(acc[mi][ni], a[mi], &b[ni >> 1][(ni & 1) * 2]);
    }
}

// fp16 warp tile 64(m) x 32(n) over one k=64 tile (rows = 128B, SW128)
__device__ __forceinline__ void warp_mma_h32(uint32_t sbA, uint32_t sbB, int wm, int wn,
                                             int lane, float (&acc)[4][4][4]) {
    int rA = lane & 15, cA = (lane & 16);
    int rB = (lane & 7) + ((lane & 16) >> 1), cB = (lane & 8) << 1;
    #pragma unroll
    for (int s = 0; s < 4; s++) {
        uint32_t a[4][4], b[2][4];
        #pragma unroll
        for (int mi = 0; mi < 4; mi++)
            ldsm4(a[mi], sbA + SWZ((wm * 64 + mi * 16 + rA) * 128 + s * 32 + cA));
        #pragma unroll
        for (int nj = 0; nj < 2; nj++)
            ldsm4(b[nj], sbB + SWZ((wn * 32 + nj * 16 + rB) * 128 + s * 32 + cB));
        #pragma unroll
        for (int mi = 0; mi < 4; mi++)
            #pragma unroll
            for (int ni = 0; ni < 4; ni++)
                mma_h(acc[mi][ni], a[mi], &b[ni >> 1][(ni & 1) * 2]);
    }
}

__device__ __forceinline__ void store_acc64f(float* out, int ld, float (&acc)[4][8][4],
                                             int wm, int wn, int lane) {
    int r0 = wm * 64 + (lane >> 2), col0 = wn * 64 + 2 * (lane & 3);
    #pragma unroll
    for (int mi = 0; mi < 4; mi++)
        #pragma unroll
        for (int ni = 0; ni < 8; ni++) {
            float* c = acc[mi][ni];
            *(float2*)&out[(size_t)(r0 + mi * 16) * ld + col0 + ni * 8] = make_float2(c[0], c[1]);
            *(float2*)&out[(size_t)(r0 + mi * 16 + 8) * ld + col0 + ni * 8] = make_float2(c[2], c[3]);
        }
}
__device__ __forceinline__ void store_acc64h(__half* out, int ld, float (&acc)[4][8][4],
                                             int wm, int wn, int lane) {
    int r0 = wm * 64 + (lane >> 2), col0 = wn * 64 + 2 * (lane & 3);
    #pragma unroll
    for (int mi = 0; mi < 4; mi++)
        #pragma unroll
        for (int ni = 0; ni < 8; ni++) {
            float* c = acc[mi][ni];
            *(__half2*)&out[(size_t)(r0 + mi * 16) * ld + col0 + ni * 8] = __floats2half2_rn(c[0], c[1]);
            *(__half2*)&out[(size_t)(r0 + mi * 16 + 8) * ld + col0 + ni * 8] = __floats2half2_rn(c[2], c[3]);
        }
}
__device__ __forceinline__ void store_acc32h(__half* out, int ld, float (&acc)[4][4][4],
                                             int wm, int wn, int lane) {
    int r0 = wm * 64 + (lane >> 2), col0 = wn * 32 + 2 * (lane & 3);
    #pragma unroll
    for (int mi = 0; mi < 4; mi++)
        #pragma unroll
        for (int ni = 0; ni < 4; ni++) {
            float* c = acc[mi][ni];
            *(__half2*)&out[(size_t)(r0 + mi * 16) * ld + col0 + ni * 8] = __floats2half2_rn(c[0], c[1]);
            *(__half2*)&out[(size_t)(r0 + mi * 16 + 8) * ld + col0 + ni * 8] = __floats2half2_rn(c[2], c[3]);
        }
}

// ---------------------------------------------------------------------------
// 1) FUSED pre pass. Long-pole colstats blocks FIRST (bid < 128) so they
//    start in wave 0 and overlap with the cvt stream; cvt blocks follow.
// ---------------------------------------------------------------------------
#define WF4  (OO * CC / 4)
#define X1F4 (BB * NN * CC / 4)
#define NB_CVT ((WF4 + X1F4) / 256)
__global__ void pre_k(const float* __restrict__ w, const float* __restrict__ x1,
                      const float* __restrict__ x2) {
    int bid = blockIdx.x;
    if (bid < 128) {
        // column softmax stats for "key": per (b, ch) max & 1/sumexp over N
        int b = bid >> 5;
        int chb = bid & 31;
        int tx = threadIdx.x & 31, ty = threadIdx.x >> 5;   // (32, 8)
        int ch = chb * 32 + tx;
        const float* p = x2 + (size_t)b * NN * CC + ch;
        float m = -1e30f, s = 0.f;
        for (int n = ty; n < NN; n += 8) {
            float v = p[(size_t)n * CC];
            float mn = fmaxf(m, v);
            s = s * __expf(m - mn) + __expf(v - mn);
            m = mn;
        }
        __shared__ float sm_[8][32], ss_[8][32];
        sm_[ty][tx] = m;
        ss_[ty][tx] = s;
        __syncthreads();
        if (ty == 0) {
            for (int r = 1; r < 8; r++) {
                float m2 = sm_[r][tx], s2 = ss_[r][tx];
                float mn = fmaxf(m, m2);
                s = s * __expf(m - mn) + s2 * __expf(m2 - mn);
                m = mn;
            }
            g_cmax[b * CC + ch] = m;
            g_cinv[b * CC + ch] = 1.f / s;
        }
        return;
    }
    int i = (bid - 128) * 256 + threadIdx.x;
    if (i < WF4) {
        float4 v = ((const float4*)w)[i];
        ((__half2*)g_wh)[2 * i] = __floats2half2_rn(v.x, v.y);
        ((__half2*)g_wh)[2 * i + 1] = __floats2half2_rn(v.z, v.w);
    } else {
        int j = i - WF4;
        float4 v = ((const float4*)x1)[j];
        ((__half2*)g_x1h)[2 * j] = __floats2half2_rn(v.x, v.y);
        ((__half2*)g_x1h)[2 * j + 1] = __floats2half2_rn(v.z, v.w);
    }
}

// ---------------------------------------------------------------------------
// 2) Prep: transpose + both softmaxes, write Q, K as [b,h,c,N] fp16
// ---------------------------------------------------------------------------
__global__ void prep_k(const float* __restrict__ x2) {
    __shared__ float t[HC][33];
    __shared__ float tmx[32], tsi[32];
    int b = blockIdx.y, n0 = blockIdx.x * 32;
    int tid = threadIdx.x;
    int w = tid >> 5, l = tid & 31;
    for (int hd = 0; hd < NH; hd++) {
        const float* src = x2 + ((size_t)(b * NN + n0)) * CC + hd * HC;
        #pragma unroll
        for (int k = 0; k < 16; k++) {
            int e = tid + 256 * k; int i = e & 127, tt = e >> 7;
            t[i][tt] = src[(size_t)tt * CC + i];
        }
        __syncthreads();
        #pragma unroll
        for (int q = 0; q < 4; q++) {
            int tok = w * 4 + q;
            float v0 = t[l][tok], v1 = t[l + 32][tok], v2 = t[l + 64][tok], v3 = t[l + 96][tok];
            float m = fmaxf(fmaxf(v0, v1), fmaxf(v2, v3));
            #pragma unroll
            for (int o = 16; o; o >>= 1) m = fmaxf(m, __shfl_xor_sync(0xffffffffu, m, o));
            float s = __expf(v0 - m) + __expf(v1 - m) + __expf(v2 - m) + __expf(v3 - m);
            #pragma unroll
            for (int o = 16; o; o >>= 1) s += __shfl_xor_sync(0xffffffffu, s, o);
            if (l == 0) { tmx[tok] = m; tsi[tok] = 1.f / s; }
        }
        __syncthreads();
        __half* Qd = g_Qh + ((size_t)(b * NH + hd)) * HC * NN + n0;
        __half* Kd = g_Kh + ((size_t)(b * NH + hd)) * HC * NN + n0;
        const float* cm = g_cmax + b * CC + hd * HC;
        const float* ci = g_cinv + b * CC + hd * HC;
        #pragma unroll
        for (int k = 0; k < 8; k++) {
            int e = tid + 256 * k;
            int tp = (e & 15) * 2, i = e >> 4;
            float va = t[i][tp], vb = t[i][tp + 1];
            float qa = __expf(va - tmx[tp]) * tsi[tp];
            float qb = __expf(vb - tmx[tp + 1]) * tsi[tp + 1];
            float ka = __expf(va - cm[i]) * ci[i];
            float kb = __expf(vb - cm[i]) * ci[i];
            *(__half2*)(Qd + (size_t)i * NN + tp) = __floats2half2_rn(qa, qb);
            *(__half2*)(Kd + (size_t)i * NN + tp) = __floats2half2_rn(ka, kb);
        }
        __syncthreads();
    }
}

// ---------------------------------------------------------------------------
// 3) GEMM1 (split-K): Sp^T[seg][j][i] = K_j . Q_i   M=128(j) N=128(i) K=512
// ---------------------------------------------------------------------------
__global__ void __launch_bounds__(128) gemm1_k() {
    extern __shared__ char smbuf[];
    uint32_t sb = s2u(smbuf);
    int tid = threadIdx.x, lane = tid & 31, wid = tid >> 5;
    int wm = wid >> 1, wn = wid & 1;
    int seg = blockIdx.x, bh = blockIdx.y;
    const __half* Ag = g_Kh + (size_t)bh * HC * NN;
    const __half* Bg = g_Qh + (size_t)bh * HC * NN;
    int kbase = seg * (NN / NSEG);
    float acc[4][8][4] = {};
    for (int q = tid; q < 1024; q += 128) {
        int r = q >> 3, c = q & 7;
        cp16(sb + SWZ(r * 128 + c * 16), Ag + (size_t)r * NN + kbase + c * 8);
        cp16(sb + 16384 + SWZ(r * 128 + c * 16), Bg + (size_t)r * NN + kbase + c * 8);
    }
    CP_COMMIT();
    for (int t = 0; t < 8; t++) {
        if (t + 1 < 8) {
            uint32_t nb = sb + ((t + 1) & 1) * 32768;
            int k0 = kbase + (t + 1) * 64;
            for (int q = tid; q < 1024; q += 128) {
                int r = q >> 3, c = q & 7;
                cp16(nb + SWZ(r * 128 + c * 16), Ag + (size_t)r * NN + k0 + c * 8);
                cp16(nb + 16384 + SWZ(r * 128 + c * 16), Bg + (size_t)r * NN + k0 + c * 8);
            }
            CP_COMMIT();
            CP_WAIT1();
        } else CP_WAIT0();
        __syncthreads();
        uint32_t cb = sb + (t & 1) * 32768;
        warp_mma_h64(cb, cb + 16384, wm, wn, lane, acc);
        __syncthreads();
    }
    float* out = g_Sp + ((size_t)(seg * BB * NH + bh)) * HC * HC;
    store_acc64f(out, HC, acc, wm, wn, lane);
}

// Vectorized split-K reduce: one float4 per thread across 8 segments
__global__ void reduceS_k() {
    int i4 = blockIdx.x * 256 + threadIdx.x;     // float4 index
    float4 s = ((const float4*)g_Sp)[i4];
    #pragma unroll
    for (int r = 1; r < NSEG; r++) {
        float4 v = ((const float4*)g_Sp)[(size_t)r * (BB * NH * HC * HC / 4) + i4];
        s.x += v.x; s.y += v.y; s.z += v.z; s.w += v.w;
    }
    __half2 lo = __floats2half2_rn(s.x, s.y);
    __half2 hi = __floats2half2_rn(s.z, s.w);
    ((__half2*)g_Sh)[2 * i4] = lo;
    ((__half2*)g_Sh)[2 * i4 + 1] = hi;
}

// ---------------------------------------------------------------------------
// 4) GEMMT: T[b][o][h*128+j] = sum_c w[o, h*128+c] * S[c,j]
// ---------------------------------------------------------------------------
__global__ void __launch_bounds__(128) gemmT_k() {
    extern __shared__ char smbuf[];
    uint32_t sb = s2u(smbuf);
    int tid = threadIdx.x, lane = tid & 31, wid = tid >> 5;
    int wm = wid >> 1, wn = wid & 1;
    int o0 = blockIdx.x * 128, bh = blockIdx.y;
    int b = bh >> 3, hd = bh & 7;
    const __half* Ag = g_wh + (size_t)o0 * CC + hd * HC;
    const __half* Bg = g_Sh + (size_t)bh * HC * HC;
    float acc[4][8][4] = {};
    for (int q = tid; q < 1024; q += 128) {
        int r = q >> 3, c = q & 7;
        cp16(sb + SWZ(r * 128 + c * 16), Ag + (size_t)r * CC + c * 8);
        cp16(sb + 16384 + SWZ(r * 128 + c * 16), Bg + (size_t)r * HC + c * 8);
    }
    CP_COMMIT();
    for (int t = 0; t < 2; t++) {
        if (t + 1 < 2) {
            int k0 = (t + 1) * 64;
            uint32_t nb = sb + 32768;
            for (int q = tid; q < 1024; q += 128) {
                int r = q >> 3, c = q & 7;
                cp16(nb + SWZ(r * 128 + c * 16), Ag + (size_t)r * CC + k0 + c * 8);
                cp16(nb + 16384 + SWZ(r * 128 + c * 16), Bg + (size_t)r * HC + k0 + c * 8);
            }
            CP_COMMIT();
            CP_WAIT1();
        } else CP_WAIT0();
        __syncthreads();
        uint32_t cb = sb + (t & 1) * 32768;
        warp_mma_h64(cb, cb + 16384, wm, wn, lane, acc);
        __syncthreads();
    }
    __half* out = g_Th + ((size_t)b * OO + o0) * CC + hd * HC;
    store_acc64h(out, CC, acc, wm, wn, lane);
}

// ---------------------------------------------------------------------------
// 5) GEMMF (dominant, at HMMA issue floor): y[n][o] = sum_c' x1h[n][c'] * T[b][o][c']
//    M=128(tok) N=256(o) K=1024; 512 threads (16 warps, warp tile 64x32),
//    2-stage k=64 double buffering, SW128.  (R8-proven configuration)
// ---------------------------------------------------------------------------
__global__ void __launch_bounds__(512) gemmF_k() {
    extern __shared__ char smbuf[];
    uint32_t sb = s2u(smbuf);
    int tid = threadIdx.x, lane = tid & 31, wid = tid >> 5;
    int wm = wid & 1, wn = wid >> 1;     // wm 0..1 (64 rows each), wn 0..7 (32 cols each)
    int m0 = blockIdx.x * 128, o0 = blockIdx.y * 256;
    int b = m0 >> 12;
    const __half* Ag = g_x1h + (size_t)m0 * CC;
    const __half* Bg = g_Th + ((size_t)b * OO + o0) * CC;
    float acc[4][4][4] = {};
    // buffers: stride 49152; A @ +0 (16KB), B @ +16384 (32KB)
    for (int q = tid; q < 1024; q += 512) {
        int r = q >> 3, c = q & 7;
        cp16(sb + SWZ(r * 128 + c * 16), Ag + (size_t)r * CC + c * 8);
    }
    for (int q = tid; q < 2048; q += 512) {
        int r = q >> 3, c = q & 7;
        cp16(sb + 16384 + SWZ(r * 128 + c * 16), Bg + (size_t)r * CC + c * 8);
    }
    CP_COMMIT();
    for (int t = 0; t < 16; t++) {
        if (t + 1 < 16) {
            int k0 = (t + 1) * 64;
            uint32_t nb = sb + ((t + 1) & 1) * 49152;
            for (int q = tid; q < 1024; q += 512) {
                int r = q >> 3, c = q & 7;
                cp16(nb + SWZ(r * 128 + c * 16), Ag + (size_t)r * CC + k0 + c * 8);
            }
            for (int q = tid; q < 2048; q += 512) {
                int r = q >> 3, c = q & 7;
                cp16(nb + 16384 + SWZ(r * 128 + c * 16), Bg + (size_t)r * CC + k0 + c * 8);
            }
            CP_COMMIT();
            CP_WAIT1();
        } else CP_WAIT0();
        __syncthreads();
        uint32_t cb = sb + (t & 1) * 49152;
        warp_mma_h32(cb, cb + 16384, wm, wn, lane, acc);
        __syncthreads();
    }
    __half* out = g_yh + (size_t)m0 * OO + o0;
    store_acc32h(out, OO, acc, wm, wn, lane);
}

// ---------------------------------------------------------------------------
// 6) Fused bias + LayerNorm over O=2048 (reads fp16 y)
// ---------------------------------------------------------------------------
__global__ void ln_k(float* __restrict__ out, const float* __restrict__ bp,
                     const float* __restrict__ gm, const float* __restrict__ bt) {
    int t = blockIdx.x;
    const __half2* y2 = (const __half2*)(g_yh + (size_t)t * OO);
    int tid = threadIdx.x;
    float v[8];
    float s = 0.f, sq = 0.f;
    #pragma unroll
    for (int k = 0; k < 4; k++) {
        int idx = tid + 256 * k;
        float2 xv = __half22float2(y2[idx]);
        float xa = xv.x + bp[2 * idx], xb = xv.y + bp[2 * idx + 1];
        v[2 * k] = xa; v[2 * k + 1] = xb;
        s += xa + xb; sq += xa * xa + xb * xb;
    }
    #pragma unroll
    for (int o = 16; o; o >>= 1) {
        s += __shfl_xor_sync(0xffffffffu, s, o);
        sq += __shfl_xor_sync(0xffffffffu, sq, o);
    }
    __shared__ float rs[8], rq[8];
    if ((tid & 31) == 0) { rs[tid >> 5] = s; rq[tid >> 5] = sq; }
    __syncthreads();
    if (tid < 8) {
        float a = rs[tid], b2 = rq[tid];
        #pragma unroll
        for (int o = 4; o; o >>= 1) {
            a += __shfl_xor_sync(0x000000ffu, a, o);
            b2 += __shfl_xor_sync(0x000000ffu, b2, o);
        }
        if (tid == 0) { rs[0] = a; rq[0] = b2; }
    }
    __syncthreads();
    float mean = rs[0] * (1.f / OO);
    float var = rq[0] * (1.f / OO) - mean * mean;
    float rstd = rsqrtf(var + 1e-5f);
    float* op = out + (size_t)t * OO;
    #pragma unroll
    for (int k = 0; k < 4; k++) {
        int idx = tid + 256 * k;
        int o = 2 * idx;
        float2 r = make_float2((v[2 * k] - mean) * rstd * gm[o] + bt[o],
                               (v[2 * k + 1] - mean) * rstd * gm[o + 1] + bt[o + 1]);
        *(float2*)&op[o] = r;
    }
}

extern "C" void kernel_launch(void* const* d_in, const int* in_sizes, int n_in,
                              void* d_out, int out_size) {
    const float* x1 = (const float*)d_in[0];
    const float* x2 = (const float*)d_in[1];
    const float* w  = (const float*)d_in[2];
    const float* bp = (const float*)d_in[3];
    const float* gm = (const float*)d_in[4];
    const float* bt = (const float*)d_in[5];
    float* out = (float*)d_out;

    const int SMG = 65536;   // gemm1/gemmT: 2 x (16KB + 16KB)
    const int SMF = 98304;   // gemmF: 2 x (16KB + 32KB)
    cudaFuncSetAttribute(gemm1_k, cudaFuncAttributeMaxDynamicSharedMemorySize, SMG);
    cudaFuncSetAttribute(gemmT_k, cudaFuncAttributeMaxDynamicSharedMemorySize, SMG);
    cudaFuncSetAttribute(gemmF_k, cudaFuncAttributeMaxDynamicSharedMemorySize, SMF);

    pre_k<<<NB_CVT + 128, 256>>>(w, x1, x2);
    prep_k<<<dim3(NN / 32, BB), 256>>>(x2);
    gemm1_k<<<dim3(NSEG, BB * NH), 128, SMG>>>();
    reduceS_k<<<(BB * NH * HC * HC / 4) / 256, 256>>>();
    gemmT_k<<<dim3(OO / 128, BB * NH), 128, SMG>>>();
    gemmF_k<<<dim3(BB * NN / 128, OO / 256), 512, SMF>>>();
    ln_k<<<BB * NN, 256>>>(out, bp, gm, bt);
}